// round 4
// baseline (speedup 1.0000x reference)
#include <cuda_runtime.h>

#define SEQ   2048
#define NB    4
#define DM    1024
#define DP    256
#define BM    128
#define BN    128
#define BK    16
#define SPAD  132   // padded smem row stride (floats), multiple of 4 for float4

// scratch for h = relu(hidden @ proj_w^T + b): [4*2048, 256] fp32 = 8 MB
__device__ float g_h[(size_t)NB * SEQ * DP];

// ---------------------------------------------------------------------------
// GEMM1 (NT): g_h[m][n] = relu( sum_d A[m][d] * W[n][d] + bias[n] )
//   A = hidden flattened [8192, 1024], W = proj_w [256, 1024]
// ---------------------------------------------------------------------------
__global__ __launch_bounds__(256) void proj_kernel(
    const float* __restrict__ A,
    const float* __restrict__ W,
    const float* __restrict__ bias)
{
    __shared__ float As[BK][SPAD];
    __shared__ float Bs[BK][SPAD];

    const int tid = threadIdx.x;
    const int tx  = tid & 15;
    const int ty  = tid >> 4;
    const int m0  = blockIdx.y * BM;
    const int n0  = blockIdx.x * BN;

    float acc[8][8];
#pragma unroll
    for (int i = 0; i < 8; i++)
#pragma unroll
        for (int j = 0; j < 8; j++) acc[i][j] = 0.0f;

    for (int kb = 0; kb < DM; kb += BK) {
        // Load 128x16 tiles of A and W (K-major), store transposed into smem.
#pragma unroll
        for (int i = 0; i < 2; i++) {
            const int f = tid + i * 256;        // 0..511 float4 slots
            const int r = f >> 2;               // tile row 0..127
            const int c = (f & 3) << 2;         // k offset 0,4,8,12
            float4 va = *reinterpret_cast<const float4*>(A + (size_t)(m0 + r) * DM + kb + c);
            As[c + 0][r] = va.x; As[c + 1][r] = va.y;
            As[c + 2][r] = va.z; As[c + 3][r] = va.w;
            float4 vb = *reinterpret_cast<const float4*>(W + (size_t)(n0 + r) * DM + kb + c);
            Bs[c + 0][r] = vb.x; Bs[c + 1][r] = vb.y;
            Bs[c + 2][r] = vb.z; Bs[c + 3][r] = vb.w;
        }
        __syncthreads();

#pragma unroll
        for (int kk = 0; kk < BK; kk++) {
            float a[8], b[8];
#pragma unroll
            for (int i = 0; i < 8; i++) a[i] = As[kk][ty * 8 + i];
#pragma unroll
            for (int j = 0; j < 8; j++) b[j] = Bs[kk][tx * 8 + j];
#pragma unroll
            for (int i = 0; i < 8; i++)
#pragma unroll
                for (int j = 0; j < 8; j++) acc[i][j] += a[i] * b[j];
        }
        __syncthreads();
    }

    // Epilogue: bias + relu, store to g_h (float4, coalesced; DP=256 rows aligned)
    const int row = m0 + ty * 8;
    const int col = n0 + tx * 8;
    float bv[8];
#pragma unroll
    for (int j = 0; j < 8; j++) bv[j] = bias[col + j];
#pragma unroll
    for (int i = 0; i < 8; i++) {
        float v[8];
#pragma unroll
        for (int j = 0; j < 8; j++) {
            float t = acc[i][j] + bv[j];
            v[j] = t > 0.0f ? t : 0.0f;
        }
        float* dst = g_h + (size_t)(row + i) * DP + col;
        *reinterpret_cast<float4*>(dst)     = make_float4(v[0], v[1], v[2], v[3]);
        *reinterpret_cast<float4*>(dst + 4) = make_float4(v[4], v[5], v[6], v[7]);
    }
}

// ---------------------------------------------------------------------------
// GEMM2 (SYRK-like): out[b][i][j] = (sum_p h[b,i,p]*h[b,j,p]) * clf_w + clf_b
// Only upper-triangular tile pairs computed; lower half mirrored via smem
// transpose staging (coalesced global writes both ways).
// ---------------------------------------------------------------------------
__global__ __launch_bounds__(256, 2) void scores_kernel(
    const float* __restrict__ clf_w,
    const float* __restrict__ clf_b,
    float* __restrict__ out)
{
    extern __shared__ float sm[];
    float (*As)[SPAD] = reinterpret_cast<float (*)[SPAD]>(sm);
    float (*Bs)[SPAD] = reinterpret_cast<float (*)[SPAD]>(sm + BK * SPAD);
    float (*Cs)[SPAD] = reinterpret_cast<float (*)[SPAD]>(sm + 2 * BK * SPAD);

    const int tid = threadIdx.x;
    const int tx  = tid & 15;
    const int ty  = tid >> 4;
    const int bat = blockIdx.y;

    // decode triangular tile pair (bi <= bj) from linear index 0..135
    int t = blockIdx.x, bi = 0;
    while (t >= 16 - bi) { t -= 16 - bi; bi++; }
    const int bj = bi + t;

    const float* H  = g_h + (size_t)bat * SEQ * DP;
    const float* Ha = H + (size_t)bi * BM * DP;
    const float* Hb = H + (size_t)bj * BM * DP;

    float acc[8][8];
#pragma unroll
    for (int i = 0; i < 8; i++)
#pragma unroll
        for (int j = 0; j < 8; j++) acc[i][j] = 0.0f;

    for (int kb = 0; kb < DP; kb += BK) {
#pragma unroll
        for (int i = 0; i < 2; i++) {
            const int f = tid + i * 256;
            const int r = f >> 2;
            const int c = (f & 3) << 2;
            float4 va = *reinterpret_cast<const float4*>(Ha + (size_t)r * DP + kb + c);
            As[c + 0][r] = va.x; As[c + 1][r] = va.y;
            As[c + 2][r] = va.z; As[c + 3][r] = va.w;
            float4 vb = *reinterpret_cast<const float4*>(Hb + (size_t)r * DP + kb + c);
            Bs[c + 0][r] = vb.x; Bs[c + 1][r] = vb.y;
            Bs[c + 2][r] = vb.z; Bs[c + 3][r] = vb.w;
        }
        __syncthreads();

#pragma unroll
        for (int kk = 0; kk < BK; kk++) {
            float a[8], b[8];
#pragma unroll
            for (int i = 0; i < 8; i++) a[i] = As[kk][ty * 8 + i];
#pragma unroll
            for (int j = 0; j < 8; j++) b[j] = Bs[kk][tx * 8 + j];
#pragma unroll
            for (int i = 0; i < 8; i++)
#pragma unroll
                for (int j = 0; j < 8; j++) acc[i][j] += a[i] * b[j];
        }
        __syncthreads();
    }

    const float scale = clf_w[0];
    const float beta  = clf_b[0];
#pragma unroll
    for (int i = 0; i < 8; i++)
#pragma unroll
        for (int j = 0; j < 8; j++) acc[i][j] = acc[i][j] * scale + beta;

    float* C = out + (size_t)bat * SEQ * SEQ;
    const int r0 = bi * BM + ty * 8;
    const int c0 = bj * BN + tx * 8;

    // direct tile (bi, bj): coalesced float4 stores from registers
#pragma unroll
    for (int i = 0; i < 8; i++) {
        float* dst = C + (size_t)(r0 + i) * SEQ + c0;
        *reinterpret_cast<float4*>(dst)     = make_float4(acc[i][0], acc[i][1], acc[i][2], acc[i][3]);
        *reinterpret_cast<float4*>(dst + 4) = make_float4(acc[i][4], acc[i][5], acc[i][6], acc[i][7]);
    }

    if (bi != bj) {
        // stage tile into smem (row-major), then write transpose coalesced
#pragma unroll
        for (int i = 0; i < 8; i++) {
            float* d = &Cs[ty * 8 + i][tx * 8];
            *reinterpret_cast<float4*>(d)     = make_float4(acc[i][0], acc[i][1], acc[i][2], acc[i][3]);
            *reinterpret_cast<float4*>(d + 4) = make_float4(acc[i][4], acc[i][5], acc[i][6], acc[i][7]);
        }
        __syncthreads();
        // mirror tile (bj, bi): element (rp, cp) = Cs[cp][rp]
#pragma unroll 8
        for (int e = 0; e < 64; e++) {
            const int idx = e * 256 + tid;
            const int rp  = idx >> 7;
            const int cp  = idx & 127;
            C[(size_t)(bj * BM + rp) * SEQ + bi * BM + cp] = Cs[cp][rp];
        }
    }
}

// ---------------------------------------------------------------------------
extern "C" void kernel_launch(void* const* d_in, const int* in_sizes, int n_in,
                              void* d_out, int out_size)
{
    const float* hidden = (const float*)d_in[0];
    const float* proj_w = (const float*)d_in[1];
    const float* proj_b = (const float*)d_in[2];
    const float* clf_w  = (const float*)d_in[3];
    const float* clf_b  = (const float*)d_in[4];
    float* out = (float*)d_out;

    dim3 g1(DP / BN, (NB * SEQ) / BM);   // (2, 64)
    proj_kernel<<<g1, 256>>>(hidden, proj_w, proj_b);

    const int smem_bytes = (2 * BK * SPAD + BM * SPAD) * (int)sizeof(float);  // 84480
    cudaFuncSetAttribute(scores_kernel,
                         cudaFuncAttributeMaxDynamicSharedMemorySize, smem_bytes);
    dim3 g2(136, NB);                    // 136 triangular tile pairs x 4 batches
    scores_kernel<<<g2, 256, smem_bytes>>>(clf_w, clf_b, out);
}

// round 6
// speedup vs baseline: 2.3060x; 2.3060x over previous
#include <cuda_runtime.h>
#include <cuda_bf16.h>
#include <cstdint>

#define SEQ 2048
#define NB  4
#define DM  1024
#define DP  256

// ---------------- bf16-split copies (device scratch, ~41 MB) ----------------
__device__ __nv_bfloat16 g_hid_hi[(size_t)NB * SEQ * DM];   // 16 MB
__device__ __nv_bfloat16 g_hid_lo[(size_t)NB * SEQ * DM];   // 16 MB
__device__ __nv_bfloat16 g_w_hi[DP * DM];                   // 512 KB
__device__ __nv_bfloat16 g_w_lo[DP * DM];                   // 512 KB
__device__ __nv_bfloat16 g_h_hi[(size_t)NB * SEQ * DP];     // 4 MB
__device__ __nv_bfloat16 g_h_lo[(size_t)NB * SEQ * DP];     // 4 MB

// ============================ PTX helpers ====================================
__device__ __forceinline__ uint32_t smem_u32(const void* p) {
    uint32_t a;
    asm("{ .reg .u64 t; cvta.to.shared.u64 t, %1; cvt.u32.u64 %0, t; }" : "=r"(a) : "l"(p));
    return a;
}
__device__ __forceinline__ void cp16(uint32_t s, const void* g) {
    asm volatile("cp.async.cg.shared.global [%0], [%1], 16;" :: "r"(s), "l"(g));
}
#define CP_COMMIT() asm volatile("cp.async.commit_group;" ::: "memory")
#define CP_WAIT1()  asm volatile("cp.async.wait_group 1;"  ::: "memory")
#define CP_WAIT0()  asm volatile("cp.async.wait_group 0;"  ::: "memory")

__device__ __forceinline__ void ldsm4(uint32_t* r, uint32_t addr) {
    asm volatile("ldmatrix.sync.aligned.m8n8.x4.shared.b16 {%0,%1,%2,%3}, [%4];"
                 : "=r"(r[0]), "=r"(r[1]), "=r"(r[2]), "=r"(r[3]) : "r"(addr));
}
__device__ __forceinline__ void mma_bf16(float* d, const uint32_t* a, const uint32_t* b) {
    asm volatile("mma.sync.aligned.m16n8k16.row.col.f32.bf16.bf16.f32 "
                 "{%0,%1,%2,%3}, {%4,%5,%6,%7}, {%8,%9}, {%0,%1,%2,%3};"
                 : "+f"(d[0]), "+f"(d[1]), "+f"(d[2]), "+f"(d[3])
                 : "r"(a[0]), "r"(a[1]), "r"(a[2]), "r"(a[3]), "r"(b[0]), "r"(b[1]));
}

// smem stage layout: 4 tiles (Ah, Al, Bh, Bl), each 128 rows x 64 B (K=32 bf16)
#define TILE_B   8192
#define STAGE_B  (4 * TILE_B)    // 32 KB; 2 stages = 64 KB
#define OFF_AH   0
#define OFF_AL   TILE_B
#define OFF_BH   (2 * TILE_B)
#define OFF_BL   (3 * TILE_B)

// swizzled in-tile byte offset for (row, c16): conflict-free for STS.128 + ldmatrix
#define SWZ(row, c16) ((uint32_t)((row) * 64) + ((uint32_t)((c16) ^ (((row) >> 1) & 3)) << 4))

// fill one stage: tiles of A(rows m) and B(rows n), K-chunk at elem offset kb
__device__ __forceinline__ void fill_stage(
    uint32_t sbase,
    const __nv_bfloat16* Ah, const __nv_bfloat16* Al,
    const __nv_bfloat16* Bh, const __nv_bfloat16* Bl,
    int kb, int kstride, int tid)
{
#pragma unroll
    for (int i = 0; i < 2; i++) {
        const int idx = tid + i * 256;      // 0..511
        const int r   = idx >> 2;
        const int c16 = idx & 3;
        const uint32_t sw = SWZ(r, c16);
        const size_t  go  = (size_t)r * kstride + kb + c16 * 8;
        cp16(sbase + OFF_AH + sw, Ah + go);
        cp16(sbase + OFF_AL + sw, Al + go);
        cp16(sbase + OFF_BH + sw, Bh + go);
        cp16(sbase + OFF_BL + sw, Bl + go);
    }
}

// compute one K=32 chunk: acc[fm][fn] += Ah*Bh + Ah*Bl + Al*Bh (warp tile 64x32)
__device__ __forceinline__ void compute_chunk(
    uint32_t sbase, int lid, int mwarp, int nwarp, float acc[4][4][4])
{
    const int rA = mwarp + (lid & 15);
    const int xA = (rA >> 1) & 3;
    const int cA = (lid >> 4);              // 0/1 -> k-low/high 16B within kstep
    const int rB = nwarp + ((lid >> 4) << 3) + (lid & 7);
    const int xB = (rB >> 1) & 3;
    const int cB = (lid >> 3) & 1;

#pragma unroll
    for (int kk = 0; kk < 2; kk++) {
        uint32_t ah[4][4], al[4][4];
#pragma unroll
        for (int fm = 0; fm < 4; fm++) {
            const uint32_t base = sbase + (uint32_t)((rA + fm * 16) * 64)
                                + ((uint32_t)((kk * 2 + cA) ^ xA) << 4);
            ldsm4(ah[fm], base + OFF_AH);
            ldsm4(al[fm], base + OFF_AL);
        }
        uint32_t bh[2][4], bl[2][4];
#pragma unroll
        for (int p = 0; p < 2; p++) {
            const uint32_t base = sbase + (uint32_t)((rB + p * 16) * 64)
                                + ((uint32_t)((kk * 2 + cB) ^ xB) << 4);
            ldsm4(bh[p], base + OFF_BH);
            ldsm4(bl[p], base + OFF_BL);
        }
#pragma unroll
        for (int fm = 0; fm < 4; fm++)
#pragma unroll
            for (int fn = 0; fn < 4; fn++) {
                const uint32_t* bhp = &bh[fn >> 1][(fn & 1) * 2];
                const uint32_t* blp = &bl[fn >> 1][(fn & 1) * 2];
                mma_bf16(acc[fm][fn], ah[fm], bhp);
                mma_bf16(acc[fm][fn], ah[fm], blp);
                mma_bf16(acc[fm][fn], al[fm], bhp);
            }
    }
}

// ======================= split conversion kernel =============================
__global__ __launch_bounds__(256) void split_kernel(
    const float* __restrict__ src, __nv_bfloat16* __restrict__ hi,
    __nv_bfloat16* __restrict__ lo)
{
    const size_t i = (size_t)blockIdx.x * 256 + threadIdx.x;   // float4 index
    float4 v = reinterpret_cast<const float4*>(src)[i];
    __nv_bfloat162 h01, h23, l01, l23;
    float f[4] = {v.x, v.y, v.z, v.w};
    __nv_bfloat16 hb[4], lb[4];
#pragma unroll
    for (int j = 0; j < 4; j++) {
        hb[j] = __float2bfloat16(f[j]);
        lb[j] = __float2bfloat16(f[j] - __bfloat162float(hb[j]));
    }
    h01 = __nv_bfloat162(hb[0], hb[1]); h23 = __nv_bfloat162(hb[2], hb[3]);
    l01 = __nv_bfloat162(lb[0], lb[1]); l23 = __nv_bfloat162(lb[2], lb[3]);
    reinterpret_cast<__nv_bfloat162*>(hi)[i * 2 + 0] = h01;
    reinterpret_cast<__nv_bfloat162*>(hi)[i * 2 + 1] = h23;
    reinterpret_cast<__nv_bfloat162*>(lo)[i * 2 + 0] = l01;
    reinterpret_cast<__nv_bfloat162*>(lo)[i * 2 + 1] = l23;
}

// =============================================================================
// GEMM1: h = relu(hidden @ W^T + bias), bf16-split HMMA, emits h hi/lo split
// =============================================================================
__global__ __launch_bounds__(256, 1) void proj_kernel(const float* __restrict__ bias)
{
    extern __shared__ char sm[];
    const uint32_t sbase = smem_u32(sm);
    const int tid = threadIdx.x, lid = tid & 31, wid = tid >> 5;
    const int mwarp = (wid >> 2) * 64, nwarp = (wid & 3) * 32;
    const int m0 = blockIdx.y * 128, n0 = blockIdx.x * 128;

    const __nv_bfloat16* Ah = g_hid_hi + (size_t)m0 * DM;
    const __nv_bfloat16* Al = g_hid_lo + (size_t)m0 * DM;
    const __nv_bfloat16* Bh = g_w_hi + (size_t)n0 * DM;
    const __nv_bfloat16* Bl = g_w_lo + (size_t)n0 * DM;

    float acc[4][4][4];
#pragma unroll
    for (int a = 0; a < 4; a++)
#pragma unroll
        for (int b = 0; b < 4; b++)
#pragma unroll
            for (int c = 0; c < 4; c++) acc[a][b][c] = 0.0f;

    const int NC = DM / 32;   // 32 chunks
    fill_stage(sbase, Ah, Al, Bh, Bl, 0, DM, tid);
    CP_COMMIT();
    for (int c = 0; c < NC; c++) {
        if (c + 1 < NC) {
            fill_stage(sbase + ((c + 1) & 1) * STAGE_B, Ah, Al, Bh, Bl,
                       (c + 1) * 32, DM, tid);
            CP_COMMIT();
            CP_WAIT1();
        } else {
            CP_WAIT0();
        }
        __syncthreads();
        compute_chunk(sbase + (c & 1) * STAGE_B, lid, mwarp, nwarp, acc);
        __syncthreads();
    }

    // epilogue: bias + relu + bf16 hi/lo split store
    const int g = lid >> 2, t = lid & 3;
#pragma unroll
    for (int fn = 0; fn < 4; fn++) {
        const int col = n0 + nwarp + fn * 8 + t * 2;
        const float2 bv = *reinterpret_cast<const float2*>(bias + col);
#pragma unroll
        for (int fm = 0; fm < 4; fm++) {
            const int row = m0 + mwarp + fm * 16 + g;
#pragma unroll
            for (int h = 0; h < 2; h++) {                 // rows g and g+8
                float x = acc[fm][fn][h * 2 + 0] + bv.x;
                float y = acc[fm][fn][h * 2 + 1] + bv.y;
                x = fmaxf(x, 0.0f); y = fmaxf(y, 0.0f);
                const __nv_bfloat16 xh = __float2bfloat16(x);
                const __nv_bfloat16 yh = __float2bfloat16(y);
                const __nv_bfloat16 xl = __float2bfloat16(x - __bfloat162float(xh));
                const __nv_bfloat16 yl = __float2bfloat16(y - __bfloat162float(yh));
                const size_t o = (size_t)(row + h * 8) * DP + col;
                *reinterpret_cast<__nv_bfloat162*>(g_h_hi + o) = __nv_bfloat162(xh, yh);
                *reinterpret_cast<__nv_bfloat162*>(g_h_lo + o) = __nv_bfloat162(xl, yl);
            }
        }
    }
}

// =============================================================================
// GEMM2: out[b][i][j] = (h_i . h_j)*clf_w + clf_b, triangular tiles + mirror
// =============================================================================
__global__ __launch_bounds__(256, 1) void scores_kernel(
    const float* __restrict__ clf_w, const float* __restrict__ clf_b,
    float* __restrict__ out)
{
    extern __shared__ char sm[];
    const uint32_t sbase = smem_u32(sm);
    const int tid = threadIdx.x, lid = tid & 31, wid = tid >> 5;
    const int mwarp = (wid >> 2) * 64, nwarp = (wid & 3) * 32;
    const int bat = blockIdx.y;

    int tt = blockIdx.x, bi = 0;
    while (tt >= 16 - bi) { tt -= 16 - bi; bi++; }
    const int bj = bi + tt;

    const size_t hb = (size_t)bat * SEQ * DP;
    const __nv_bfloat16* Ah = g_h_hi + hb + (size_t)bi * 128 * DP;
    const __nv_bfloat16* Al = g_h_lo + hb + (size_t)bi * 128 * DP;
    const __nv_bfloat16* Bh = g_h_hi + hb + (size_t)bj * 128 * DP;
    const __nv_bfloat16* Bl = g_h_lo + hb + (size_t)bj * 128 * DP;

    float acc[4][4][4];
#pragma unroll
    for (int a = 0; a < 4; a++)
#pragma unroll
        for (int b = 0; b < 4; b++)
#pragma unroll
            for (int c = 0; c < 4; c++) acc[a][b][c] = 0.0f;

    const int NC = DP / 32;   // 8 chunks
    fill_stage(sbase, Ah, Al, Bh, Bl, 0, DP, tid);
    CP_COMMIT();
    for (int c = 0; c < NC; c++) {
        if (c + 1 < NC) {
            fill_stage(sbase + ((c + 1) & 1) * STAGE_B, Ah, Al, Bh, Bl,
                       (c + 1) * 32, DP, tid);
            CP_COMMIT();
            CP_WAIT1();
        } else {
            CP_WAIT0();
        }
        __syncthreads();
        compute_chunk(sbase + (c & 1) * STAGE_B, lid, mwarp, nwarp, acc);
        __syncthreads();
    }

    const float scale = clf_w[0];
    const float beta  = clf_b[0];
    float* C = out + (size_t)bat * SEQ * SEQ;
    float (*Cs)[129] = reinterpret_cast<float (*)[129]>(sm);

    __syncthreads();   // smem A/B tiles no longer needed; reuse as Cs

    const int g = lid >> 2, t = lid & 3;
#pragma unroll
    for (int fm = 0; fm < 4; fm++)
#pragma unroll
        for (int fn = 0; fn < 4; fn++) {
            const int rl = mwarp + fm * 16 + g;
            const int cl = nwarp + fn * 8 + t * 2;
            const float v0 = acc[fm][fn][0] * scale + beta;
            const float v1 = acc[fm][fn][1] * scale + beta;
            const float v2 = acc[fm][fn][2] * scale + beta;
            const float v3 = acc[fm][fn][3] * scale + beta;
            // direct tile (bi, bj): coalesced float2 stores
            *reinterpret_cast<float2*>(C + (size_t)(bi * 128 + rl) * SEQ + bj * 128 + cl)
                = make_float2(v0, v1);
            *reinterpret_cast<float2*>(C + (size_t)(bi * 128 + rl + 8) * SEQ + bj * 128 + cl)
                = make_float2(v2, v3);
            if (bi != bj) {
                Cs[rl][cl] = v0; Cs[rl][cl + 1] = v1;
                Cs[rl + 8][cl] = v2; Cs[rl + 8][cl + 1] = v3;
            }
        }

    if (bi != bj) {
        __syncthreads();
        // mirror tile (bj, bi): coalesced writes, conflict-free smem reads
#pragma unroll 4
        for (int e = 0; e < 64; e++) {
            const int idx  = e * 256 + tid;
            const int cloc = idx >> 7;
            const int rloc = idx & 127;
            C[(size_t)(bj * 128 + cloc) * SEQ + bi * 128 + rloc] = Cs[rloc][cloc];
        }
    }
}

// =============================================================================
extern "C" void kernel_launch(void* const* d_in, const int* in_sizes, int n_in,
                              void* d_out, int out_size)
{
    const float* hidden = (const float*)d_in[0];
    const float* proj_w = (const float*)d_in[1];
    const float* proj_b = (const float*)d_in[2];
    const float* clf_w  = (const float*)d_in[3];
    const float* clf_b  = (const float*)d_in[4];
    float* out = (float*)d_out;

    __nv_bfloat16 *hid_hi, *hid_lo, *w_hi, *w_lo;
    cudaGetSymbolAddress((void**)&hid_hi, g_hid_hi);
    cudaGetSymbolAddress((void**)&hid_lo, g_hid_lo);
    cudaGetSymbolAddress((void**)&w_hi,  g_w_hi);
    cudaGetSymbolAddress((void**)&w_lo,  g_w_lo);

    split_kernel<<<(NB * SEQ * DM / 4) / 256, 256>>>(hidden, hid_hi, hid_lo);
    split_kernel<<<(DP * DM / 4) / 256, 256>>>(proj_w, w_hi, w_lo);

    const int smem_gemm = 2 * STAGE_B;                 // 64 KB
    const int smem_sc   = 128 * 129 * 4;               // 66048 > 64 KB
    cudaFuncSetAttribute(proj_kernel,
                         cudaFuncAttributeMaxDynamicSharedMemorySize, smem_gemm);
    cudaFuncSetAttribute(scores_kernel,
                         cudaFuncAttributeMaxDynamicSharedMemorySize, smem_sc);

    dim3 g1(DP / 128, (NB * SEQ) / 128);               // (2, 64)
    proj_kernel<<<g1, 256, smem_gemm>>>(proj_b);

    dim3 g2(136, NB);                                  // triangular pairs x batches
    scores_kernel<<<g2, 256, smem_sc>>>(clf_w, clf_b, out);
}

// round 8
// speedup vs baseline: 2.6666x; 1.1563x over previous
#include <cuda_runtime.h>
#include <cuda_bf16.h>
#include <cstdint>

#define SEQ 2048
#define NB  4
#define DM  1024
#define DP  256

// ---------------- bf16-split scratch -----------------------------------------
__device__ __nv_bfloat16 g_w_hi[DP * DM];                   // 512 KB
__device__ __nv_bfloat16 g_w_lo[DP * DM];                   // 512 KB
__device__ __nv_bfloat16 g_h_hi[(size_t)NB * SEQ * DP];     // 4 MB
__device__ __nv_bfloat16 g_h_lo[(size_t)NB * SEQ * DP];     // 4 MB

// ============================ PTX helpers ====================================
__device__ __forceinline__ uint32_t smem_u32(const void* p) {
    uint32_t a;
    asm("{ .reg .u64 t; cvta.to.shared.u64 t, %1; cvt.u32.u64 %0, t; }" : "=r"(a) : "l"(p));
    return a;
}
__device__ __forceinline__ void cp16(uint32_t s, const void* g) {
    asm volatile("cp.async.cg.shared.global [%0], [%1], 16;" :: "r"(s), "l"(g));
}
#define CP_COMMIT() asm volatile("cp.async.commit_group;" ::: "memory")
#define CP_WAIT1()  asm volatile("cp.async.wait_group 1;"  ::: "memory")
#define CP_WAIT0()  asm volatile("cp.async.wait_group 0;"  ::: "memory")

__device__ __forceinline__ void ldsm4(uint32_t* r, uint32_t addr) {
    asm volatile("ldmatrix.sync.aligned.m8n8.x4.shared.b16 {%0,%1,%2,%3}, [%4];"
                 : "=r"(r[0]), "=r"(r[1]), "=r"(r[2]), "=r"(r[3]) : "r"(addr));
}
__device__ __forceinline__ void mma_bf16(float* d, const uint32_t* a, const uint32_t* b) {
    asm volatile("mma.sync.aligned.m16n8k16.row.col.f32.bf16.bf16.f32 "
                 "{%0,%1,%2,%3}, {%4,%5,%6,%7}, {%8,%9}, {%0,%1,%2,%3};"
                 : "+f"(d[0]), "+f"(d[1]), "+f"(d[2]), "+f"(d[3])
                 : "r"(a[0]), "r"(a[1]), "r"(a[2]), "r"(a[3]), "r"(b[0]), "r"(b[1]));
}

// swizzled in-tile byte offset (row stride 64B, 4x16B cells per row)
#define SWZ(row, c16) ((uint32_t)((row) * 64) + ((uint32_t)((c16) ^ (((row) >> 1) & 3)) << 4))

// -------- generic K=32 compute chunk, warp tile (FM*16) x 32 -----------------
template<int FM>
__device__ __forceinline__ void compute_chunk(
    uint32_t sbase, uint32_t offAH, uint32_t offAL, uint32_t offBH, uint32_t offBL,
    int lid, int mwarp, int nwarp, float acc[FM][4][4])
{
    const int rA = mwarp + (lid & 15);
    const int xA = (rA >> 1) & 3;
    const int cA = (lid >> 4);
    const int rB = nwarp + ((lid >> 4) << 3) + (lid & 7);
    const int xB = (rB >> 1) & 3;
    const int cB = (lid >> 3) & 1;

#pragma unroll
    for (int kk = 0; kk < 2; kk++) {
        uint32_t bh[2][4], bl[2][4];
#pragma unroll
        for (int p = 0; p < 2; p++) {
            const uint32_t base = sbase + (uint32_t)((rB + p * 16) * 64)
                                + ((uint32_t)((kk * 2 + cB) ^ xB) << 4);
            ldsm4(bh[p], base + offBH);
            ldsm4(bl[p], base + offBL);
        }
#pragma unroll
        for (int fm = 0; fm < FM; fm++) {
            uint32_t ah[4], al[4];
            const uint32_t base = sbase + (uint32_t)((rA + fm * 16) * 64)
                                + ((uint32_t)((kk * 2 + cA) ^ xA) << 4);
            ldsm4(ah, base + offAH);
            ldsm4(al, base + offAL);
#pragma unroll
            for (int fn = 0; fn < 4; fn++) {
                const uint32_t* bhp = &bh[fn >> 1][(fn & 1) * 2];
                const uint32_t* blp = &bl[fn >> 1][(fn & 1) * 2];
                mma_bf16(acc[fm][fn], ah, bhp);
                mma_bf16(acc[fm][fn], ah, blp);
                mma_bf16(acc[fm][fn], al, bhp);
            }
        }
    }
}

// ======================= split conversion kernel (W only) ====================
__global__ __launch_bounds__(256) void split_kernel(
    const float* __restrict__ src, __nv_bfloat16* __restrict__ hi,
    __nv_bfloat16* __restrict__ lo)
{
    const size_t i = (size_t)blockIdx.x * 256 + threadIdx.x;   // float4 index
    float4 v = reinterpret_cast<const float4*>(src)[i];
    float f[4] = {v.x, v.y, v.z, v.w};
    __nv_bfloat16 hb[4], lb[4];
#pragma unroll
    for (int j = 0; j < 4; j++) {
        hb[j] = __float2bfloat16(f[j]);
        lb[j] = __float2bfloat16(f[j] - __bfloat162float(hb[j]));
    }
    reinterpret_cast<__nv_bfloat162*>(hi)[i * 2 + 0] = __nv_bfloat162(hb[0], hb[1]);
    reinterpret_cast<__nv_bfloat162*>(hi)[i * 2 + 1] = __nv_bfloat162(hb[2], hb[3]);
    reinterpret_cast<__nv_bfloat162*>(lo)[i * 2 + 0] = __nv_bfloat162(lb[0], lb[1]);
    reinterpret_cast<__nv_bfloat162*>(lo)[i * 2 + 1] = __nv_bfloat162(lb[2], lb[3]);
}

// =============================================================================
// GEMM1: h = relu(hidden @ W^T + bias).  Fp32 A loaded via LDG, converted to
// bf16 hi/lo in-kernel (fused split).  Tile 64M x 128N, 8 warps (32x32 each).
// =============================================================================
#define P_AH 0
#define P_AL 4096
#define P_BH 8192
#define P_BL 16384
#define P_STAGE 24576          // 24 KB; 2 stages = 48 KB

__global__ __launch_bounds__(256, 2) void proj_kernel(
    const float* __restrict__ A, const float* __restrict__ bias)
{
    extern __shared__ char sm[];
    const uint32_t sbase = smem_u32(sm);
    const int tid = threadIdx.x, lid = tid & 31, wid = tid >> 5;
    const int mwarp = (wid >> 2) * 32, nwarp = (wid & 3) * 32;
    const int m0 = blockIdx.y * 64, n0 = blockIdx.x * 128;

    const float* Ag = A + (size_t)m0 * DM;
    const __nv_bfloat16* Wh = g_w_hi + (size_t)n0 * DM;
    const __nv_bfloat16* Wl = g_w_lo + (size_t)n0 * DM;

    // this thread's A cell: row r, 16B-cell c16 (64 rows x 4 cells = 256 cells)
    const int ar  = tid >> 2;
    const int ac  = tid & 3;
    const uint32_t aswz = SWZ(ar, ac);
    const float* agp = Ag + (size_t)ar * DM + ac * 8;

    float acc[2][4][4];
#pragma unroll
    for (int a = 0; a < 2; a++)
#pragma unroll
        for (int b = 0; b < 4; b++)
#pragma unroll
            for (int c = 0; c < 4; c++) acc[a][b][c] = 0.0f;

    const int NC = DM / 32;

    // prologue: A(0) regs + W(0) cp.async
    float4 fa0 = *reinterpret_cast<const float4*>(agp);
    float4 fa1 = *reinterpret_cast<const float4*>(agp + 4);
#pragma unroll
    for (int i = 0; i < 2; i++) {
        const int idx = tid + i * 256, r = idx >> 2, c16 = idx & 3;
        const uint32_t sw = SWZ(r, c16);
        const size_t go = (size_t)r * DM + c16 * 8;
        cp16(sbase + P_BH + sw, Wh + go);
        cp16(sbase + P_BL + sw, Wl + go);
    }
    CP_COMMIT();

    for (int c = 0; c < NC; c++) {
        const uint32_t buf = sbase + (uint32_t)(c & 1) * P_STAGE;
        // convert + store A(c) into this stage
        {
            float f[8] = {fa0.x, fa0.y, fa0.z, fa0.w, fa1.x, fa1.y, fa1.z, fa1.w};
            union { __nv_bfloat16 b[8]; uint4 u; } hv, lv;
#pragma unroll
            for (int j = 0; j < 8; j++) {
                const __nv_bfloat16 h = __float2bfloat16(f[j]);
                hv.b[j] = h;
                lv.b[j] = __float2bfloat16(f[j] - __bfloat162float(h));
            }
            *reinterpret_cast<uint4*>(sm + (c & 1) * P_STAGE + P_AH + aswz) = hv.u;
            *reinterpret_cast<uint4*>(sm + (c & 1) * P_STAGE + P_AL + aswz) = lv.u;
        }
        if (c + 1 < NC) {
            const int kb = (c + 1) * 32;
            fa0 = *reinterpret_cast<const float4*>(agp + kb);
            fa1 = *reinterpret_cast<const float4*>(agp + kb + 4);
            const uint32_t nbuf = sbase + (uint32_t)((c + 1) & 1) * P_STAGE;
#pragma unroll
            for (int i = 0; i < 2; i++) {
                const int idx = tid + i * 256, r = idx >> 2, c16 = idx & 3;
                const uint32_t sw = SWZ(r, c16);
                const size_t go = (size_t)r * DM + kb + c16 * 8;
                cp16(nbuf + P_BH + sw, Wh + go);
                cp16(nbuf + P_BL + sw, Wl + go);
            }
            CP_COMMIT();
            CP_WAIT1();
        } else {
            CP_WAIT0();
        }
        __syncthreads();
        compute_chunk<2>(buf, P_AH, P_AL, P_BH, P_BL, lid, mwarp, nwarp, acc);
        __syncthreads();
    }

    // epilogue: bias + relu + bf16 hi/lo split store
    const int g = lid >> 2, t = lid & 3;
#pragma unroll
    for (int fn = 0; fn < 4; fn++) {
        const int col = n0 + nwarp + fn * 8 + t * 2;
        const float2 bv = *reinterpret_cast<const float2*>(bias + col);
#pragma unroll
        for (int fm = 0; fm < 2; fm++) {
            const int row = m0 + mwarp + fm * 16 + g;
#pragma unroll
            for (int h = 0; h < 2; h++) {
                float x = acc[fm][fn][h * 2 + 0] + bv.x;
                float y = acc[fm][fn][h * 2 + 1] + bv.y;
                x = fmaxf(x, 0.0f); y = fmaxf(y, 0.0f);
                const __nv_bfloat16 xh = __float2bfloat16(x);
                const __nv_bfloat16 yh = __float2bfloat16(y);
                const __nv_bfloat16 xl = __float2bfloat16(x - __bfloat162float(xh));
                const __nv_bfloat16 yl = __float2bfloat16(y - __bfloat162float(yh));
                const size_t o = (size_t)(row + h * 8) * DP + col;
                *reinterpret_cast<__nv_bfloat162*>(g_h_hi + o) = __nv_bfloat162(xh, yh);
                *reinterpret_cast<__nv_bfloat162*>(g_h_lo + o) = __nv_bfloat162(xl, yl);
            }
        }
    }
}

// =============================================================================
// GEMM2: out[b][i][j] = (h_i . h_j)*clf_w + clf_b.  Tile 128x128, 8 warps
// (64x32 each), triangular tile pairs + smem-transposed mirror.
// =============================================================================
#define S_TILE  8192
#define S_AH    0
#define S_AL    S_TILE
#define S_BH    (2 * S_TILE)
#define S_BL    (3 * S_TILE)
#define S_STAGE (4 * S_TILE)   // 32 KB; 2 stages = 64 KB

__device__ __forceinline__ void scores_fill(
    uint32_t sbase,
    const __nv_bfloat16* Ah, const __nv_bfloat16* Al,
    const __nv_bfloat16* Bh, const __nv_bfloat16* Bl,
    int kb, int tid)
{
#pragma unroll
    for (int i = 0; i < 2; i++) {
        const int idx = tid + i * 256;
        const int r = idx >> 2, c16 = idx & 3;
        const uint32_t sw = SWZ(r, c16);
        const size_t go = (size_t)r * DP + kb + c16 * 8;
        cp16(sbase + S_AH + sw, Ah + go);
        cp16(sbase + S_AL + sw, Al + go);
        cp16(sbase + S_BH + sw, Bh + go);
        cp16(sbase + S_BL + sw, Bl + go);
    }
}

__global__ __launch_bounds__(256, 2) void scores_kernel(
    const float* __restrict__ clf_w, const float* __restrict__ clf_b,
    float* __restrict__ out)
{
    extern __shared__ char sm[];
    const uint32_t sbase = smem_u32(sm);
    const int tid = threadIdx.x, lid = tid & 31, wid = tid >> 5;
    const int mwarp = (wid >> 2) * 64, nwarp = (wid & 3) * 32;
    const int bat = blockIdx.y;

    int tt = blockIdx.x, bi = 0;
    while (tt >= 16 - bi) { tt -= 16 - bi; bi++; }
    const int bj = bi + tt;

    const size_t hb = (size_t)bat * SEQ * DP;
    const __nv_bfloat16* Ah = g_h_hi + hb + (size_t)bi * 128 * DP;
    const __nv_bfloat16* Al = g_h_lo + hb + (size_t)bi * 128 * DP;
    const __nv_bfloat16* Bh = g_h_hi + hb + (size_t)bj * 128 * DP;
    const __nv_bfloat16* Bl = g_h_lo + hb + (size_t)bj * 128 * DP;

    float acc[4][4][4];
#pragma unroll
    for (int a = 0; a < 4; a++)
#pragma unroll
        for (int b = 0; b < 4; b++)
#pragma unroll
            for (int c = 0; c < 4; c++) acc[a][b][c] = 0.0f;

    const int NC = DP / 32;
    scores_fill(sbase, Ah, Al, Bh, Bl, 0, tid);
    CP_COMMIT();
    for (int c = 0; c < NC; c++) {
        if (c + 1 < NC) {
            scores_fill(sbase + ((c + 1) & 1) * S_STAGE, Ah, Al, Bh, Bl,
                        (c + 1) * 32, tid);
            CP_COMMIT();
            CP_WAIT1();
        } else {
            CP_WAIT0();
        }
        __syncthreads();
        compute_chunk<4>(sbase + (c & 1) * S_STAGE, S_AH, S_AL, S_BH, S_BL,
                         lid, mwarp, nwarp, acc);
        __syncthreads();
    }

    const float scale = clf_w[0];
    const float beta  = clf_b[0];
    float* C = out + (size_t)bat * SEQ * SEQ;
    float (*Cs)[129] = reinterpret_cast<float (*)[129]>(sm);

    __syncthreads();   // reuse smem as Cs

    const int g = lid >> 2, t = lid & 3;
#pragma unroll
    for (int fm = 0; fm < 4; fm++)
#pragma unroll
        for (int fn = 0; fn < 4; fn++) {
            const int rl = mwarp + fm * 16 + g;
            const int cl = nwarp + fn * 8 + t * 2;
            const float v0 = acc[fm][fn][0] * scale + beta;
            const float v1 = acc[fm][fn][1] * scale + beta;
            const float v2 = acc[fm][fn][2] * scale + beta;
            const float v3 = acc[fm][fn][3] * scale + beta;
            *reinterpret_cast<float2*>(C + (size_t)(bi * 128 + rl) * SEQ + bj * 128 + cl)
                = make_float2(v0, v1);
            *reinterpret_cast<float2*>(C + (size_t)(bi * 128 + rl + 8) * SEQ + bj * 128 + cl)
                = make_float2(v2, v3);
            if (bi != bj) {
                Cs[rl][cl] = v0; Cs[rl][cl + 1] = v1;
                Cs[rl + 8][cl] = v2; Cs[rl + 8][cl + 1] = v3;
            }
        }

    if (bi != bj) {
        __syncthreads();
#pragma unroll 4
        for (int e = 0; e < 64; e++) {
            const int idx  = e * 256 + tid;
            const int cloc = idx >> 7;
            const int rloc = idx & 127;
            C[(size_t)(bj * 128 + cloc) * SEQ + bi * 128 + rloc] = Cs[rloc][cloc];
        }
    }
}

// =============================================================================
extern "C" void kernel_launch(void* const* d_in, const int* in_sizes, int n_in,
                              void* d_out, int out_size)
{
    const float* hidden = (const float*)d_in[0];
    const float* proj_w = (const float*)d_in[1];
    const float* proj_b = (const float*)d_in[2];
    const float* clf_w  = (const float*)d_in[3];
    const float* clf_b  = (const float*)d_in[4];
    float* out = (float*)d_out;

    __nv_bfloat16 *w_hi, *w_lo;
    cudaGetSymbolAddress((void**)&w_hi, g_w_hi);
    cudaGetSymbolAddress((void**)&w_lo, g_w_lo);

    split_kernel<<<(DP * DM / 4) / 256, 256>>>(proj_w, w_hi, w_lo);

    const int smem_proj = 2 * P_STAGE;        // 48 KB
    const int smem_sc   = 128 * 129 * 4;      // 66048 (covers 64 KB stages too)
    cudaFuncSetAttribute(proj_kernel,
                         cudaFuncAttributeMaxDynamicSharedMemorySize, smem_proj);
    cudaFuncSetAttribute(scores_kernel,
                         cudaFuncAttributeMaxDynamicSharedMemorySize, smem_sc);

    dim3 g1(DP / 128, (NB * SEQ) / 64);       // (2, 128) = 256 CTAs
    proj_kernel<<<g1, 256, smem_proj>>>(hidden, proj_b);

    dim3 g2(136, NB);
    scores_kernel<<<g2, 256, smem_sc>>>(clf_w, clf_b, out);
}